// round 16
// baseline (speedup 1.0000x reference)
#include <cuda_runtime.h>

// Problem constants (fixed shapes for this problem instance)
#define NPTS     128                    // n_points
#define STEPS    64                     // velocity steps
#define NPAIRS   ((NPTS*(NPTS-1))/2)    // 8128 upper-tri pairs
#define NCH      16                     // s-chunks per (i,j) pair (non-event)
#define SCH      (STEPS/NCH)            // 4 steps per chunk (one float4)
#define TPB      256
#define PPB      (TPB/NCH)              // 16 pairs per non-event block
#define SPLIT_EV 4                      // step-splits per event pair-block
#define EV_STEPS (STEPS/SPLIT_EV)       // 16 steps per event block
#define EV_Q     (EV_STEPS/4)           // 4 float4 iters per event block
#define VSTRIDE  5                      // float4 stride per staged row (bank padding)

static __device__ __constant__ float kDELTA  = (float)(100.0 / 63.0);  // fp32 MAX_TIME/(STEPS-1)
static __device__ __constant__ float kINVD   = 0.63f;                  // 1/kDELTA (63/100), ~1ulp
static __device__ __constant__ float kEPS    = 1e-9f;
static __device__ __constant__ float kSQPI_2 = 0.8862269254527580f;    // sqrt(pi)/2
// Abramowitz & Stegun 7.1.25 erf approximation (|abs err| < 2.5e-5)
static __device__ __constant__ float kP3 = 0.47047f;
static __device__ __constant__ float kB1 = 0.3480242f;
static __device__ __constant__ float kB2 = -0.0958798f;
static __device__ __constant__ float kB3 = 0.7478556f;

// Per-block double partials + completion counter.
// g_count self-resets to 0 at end of every launch -> graph-replay deterministic.
__device__ double   g_part[1024];
__device__ unsigned g_count = 0;

// fp32 intra-warp reduce (cheap FADD tail), double only across the 8 warps.
__device__ __forceinline__ double block_reduce_f(float v, double* shd) {
    int tid = threadIdx.x;
    #pragma unroll
    for (int off = 16; off > 0; off >>= 1)
        v += __shfl_down_sync(0xffffffffu, v, off);
    if ((tid & 31) == 0) shd[tid >> 5] = (double)v;
    __syncthreads();
    double d = 0.0;
    if (tid < 8) {
        d = shd[tid];
        #pragma unroll
        for (int off = 4; off > 0; off >>= 1)
            d += __shfl_down_sync(0xffu, d, off);
    }
    return d;  // valid on tid 0
}

__device__ __forceinline__ double block_reduce_d(double v, double* sh) {
    int tid = threadIdx.x;
    #pragma unroll
    for (int off = 16; off > 0; off >>= 1)
        v += __shfl_down_sync(0xffffffffu, v, off);
    if ((tid & 31) == 0) sh[tid >> 5] = v;
    __syncthreads();
    if (tid < 8) {
        v = sh[tid];
        #pragma unroll
        for (int off = 4; off > 0; off >>= 1)
            v += __shfl_down_sync(0xffu, v, off);
    }
    return v;  // valid on tid 0
}

// L2-direct store / load (bypass L1) + acq_rel completion counter.
// No __threadfence anywhere -> no CCTL.IVALL L1 flush poisoning co-resident blocks.
__device__ __forceinline__ void st_cg_f64(double* p, double v) {
    asm volatile("st.global.cg.f64 [%0], %1;" :: "l"(p), "d"(v) : "memory");
}
__device__ __forceinline__ double ld_cg_f64(const double* p) {
    double v;
    asm volatile("ld.global.cg.f64 %0, [%1];" : "=d"(v) : "l"(p) : "memory");
    return v;
}
__device__ __forceinline__ unsigned atom_inc_acq_rel(unsigned* p) {
    unsigned d;
    asm volatile("atom.acq_rel.gpu.global.add.u32 %0, [%1], 1;"
                 : "=r"(d) : "l"(p) : "memory");
    return d;
}

__global__ void __launch_bounds__(TPB)
k_all(const float* __restrict__ beta,
      const float* __restrict__ z0,
      const float* __restrict__ v0,
      const float* __restrict__ ev,
      const int*   __restrict__ pi,
      const int*   __restrict__ pj,
      int P, int E, int NB_EV, int NB,
      float* __restrict__ out)
{
    // All shared declared at kernel scope (no branch-scope overlay surprises).
    __shared__ double sred[8];
    __shared__ bool   s_last;
    // Event branch: staged v0 quarter-slice. Comp-major + stride-5 padding:
    //   x-row of point i at sV[i*VSTRIDE], y-row at sV[(128+i)*VSTRIDE].
    __shared__ __align__(16) float4 sV[2 * NPTS * VSTRIDE];   // 20 KB
    __shared__ __align__(16) float  sZ[2 * NPTS];             // 1 KB
    __shared__ __align__(16) float  sS1[STEPS];
    __shared__ __align__(16) float  sS2[STEPS];
    // Non-event branch:
    __shared__ int   sIo[PPB], sJo[PPB];
    __shared__ float sDZX[PPB], sDZY[PPB];

    const int tid = threadIdx.x;
    float facc = 0.f;     // per-thread fp32 partial

    if ((int)blockIdx.x < NB_EV) {
        // ---------------- event (pair) term ----------------
        // block -> (pair-block pb, step-quarter)
        const int pb      = blockIdx.x >> 2;          // /SPLIT_EV
        const int quarter = blockIdx.x & (SPLIT_EV-1);
        const int lo      = quarter * EV_STEPS;       // step range [lo, lo+16)
        const int q_beg   = quarter * EV_Q;           // float4 col range in v0 rows

        if (tid < EV_STEPS) { sS1[lo + tid] = 0.f; sS2[lo + tid] = 0.f; }

        // Stage this quarter's v0 slice + z0 into shared (coalesced, one-time).
        // thread t: comp = t>>7, point = t&127; global row = 2*point + comp.
        {
            const float4* g = (const float4*)v0;       // row stride = 16 float4
            const int point = tid & (NPTS - 1);
            const int comp  = tid >> 7;
            const int grow  = 2 * point + comp;
            const int srow  = comp * NPTS + point;
            #pragma unroll
            for (int k = 0; k < EV_Q; k++)
                sV[srow * VSTRIDE + k] = g[grow * 16 + q_beg + k];
            if (tid < (2 * NPTS) / 4)
                ((float4*)sZ)[tid] = ((const float4*)z0)[tid];
        }
        __syncthreads();

        // Histogram of event times restricted to this block's step range.
        {
            const float4* ev4 = (const float4*)ev;
            const int nq = E >> 2;
            #pragma unroll
            for (int q = tid; q < nq; q += TPB) {
                float4 t4 = ev4[q];
                #pragma unroll
                for (int u = 0; u < 4; u++) {
                    float t  = (u == 0) ? t4.x : (u == 1) ? t4.y : (u == 2) ? t4.z : t4.w;
                    float tv = t * kINVD;          // ~1ulp vs ref's fp32 divide
                    float f  = floorf(tv);
                    int   s  = (int)f;
                    s = max(0, min(STEPS - 1, s));
                    if (s >= lo && s < lo + EV_STEPS) {
                        float a = (s == 0 ? 0.0f : kDELTA) + (tv - f);  // td[s] + frac
                        atomicAdd(&sS1[s], a);
                        atomicAdd(&sS2[s], a * a);
                    }
                }
            }
        }
        __syncthreads();

        const int p = pb * TPB + tid;
        if (p < P) {
            const int i = pi[p], j = pj[p];
            const float dzx = sZ[2*i]   - sZ[2*j];
            const float dzy = sZ[2*i+1] - sZ[2*j+1];
            const float4* S1 = (const float4*)sS1;
            const float4* S2 = (const float4*)sS2;
            float a0 = 0.f, a1 = 0.f, a2 = 0.f, a3 = 0.f;
            #pragma unroll
            for (int k = 0; k < EV_Q; k++) {
                float4 ax = sV[i * VSTRIDE + k];                 // x row, point i
                float4 ay = sV[(NPTS + i) * VSTRIDE + k];        // y row, point i
                float4 bx = sV[j * VSTRIDE + k];
                float4 by = sV[(NPTS + j) * VSTRIDE + k];
                float4 h1 = S1[q_beg + k], h2 = S2[q_beg + k];
                float dvx, dvy, B, C;
                dvx = ax.x - bx.x; dvy = ay.x - by.x;
                B = fmaf(dzx, dvx, dzy * dvy); C = fmaf(dvx, dvx, dvy * dvy);
                a0 += fmaf(2.0f * h1.x, B, h2.x * C);
                dvx = ax.y - bx.y; dvy = ay.y - by.y;
                B = fmaf(dzx, dvx, dzy * dvy); C = fmaf(dvx, dvx, dvy * dvy);
                a1 += fmaf(2.0f * h1.y, B, h2.y * C);
                dvx = ax.z - bx.z; dvy = ay.z - by.z;
                B = fmaf(dzx, dvx, dzy * dvy); C = fmaf(dvx, dvx, dvy * dvy);
                a2 += fmaf(2.0f * h1.z, B, h2.z * C);
                dvx = ax.w - bx.w; dvy = ay.w - by.w;
                B = fmaf(dzx, dvx, dzy * dvy); C = fmaf(dvx, dvx, dvy * dvy);
                a3 += fmaf(2.0f * h1.w, B, h2.w * C);
            }
            facc = (a0 + a1) + (a2 + a3);
            if (quarter == 0)   // E * |dz0|^2 term counted exactly once per pair
                facc += (float)E * fmaf(dzx, dzx, dzy * dzy);
        }
    } else {
        // ---------------- non-event (integral) term ----------------
        // Each block covers PPB=16 consecutive dense-tri pairs x NCH=16 chunks.
        const int base_p = (blockIdx.x - NB_EV) * PPB;

        if (tid < PPB) {
            const int p = base_p + tid;
            // Decode dense upper-tri index -> (i, j), i < j, N = 128.
            int i = (int)((255.0f - sqrtf(65025.0f - 8.0f * (float)p)) * 0.5f);
            i = max(0, min(126, i));
            int off = (i * (255 - i)) >> 1;
            if (off > p)                   { i--; off = (i * (255 - i)) >> 1; }
            else if (off + (127 - i) <= p) { off += 127 - i; i++; }
            const int j = i + 1 + (p - off);
            sIo[tid]  = 2 * i * STEPS;
            sJo[tid]  = 2 * j * STEPS;
            sDZX[tid] = z0[2*i]   - z0[2*j];
            sDZY[tid] = z0[2*i+1] - z0[2*j+1];
        }
        __syncthreads();

        const int pp    = tid >> 4;          // pair slot 0..15
        const int chunk = tid & (NCH - 1);   // 0..15
        const int io = sIo[pp], jo = sJo[pp];
        const float dzx0 = sDZX[pp], dzy0 = sDZY[pp];
        const float bb   = beta[0];
        const int s_beg  = chunk * SCH;      // multiple of 4 -> 16B aligned
        const float4 vx_i = *(const float4*)(v0 + io + s_beg);
        const float4 vy_i = *(const float4*)(v0 + io + STEPS + s_beg);
        const float4 vx_j = *(const float4*)(v0 + jo + s_beg);
        const float4 vy_j = *(const float4*)(v0 + jo + STEPS + s_beg);
        const float DVX[4] = {vx_i.x - vx_j.x, vx_i.y - vx_j.y, vx_i.z - vx_j.z, vx_i.w - vx_j.w};
        const float DVY[4] = {vy_i.x - vy_j.x, vy_i.y - vy_j.y, vy_i.z - vy_j.z, vy_i.w - vy_j.w};

        float accs[4];
        #pragma unroll
        for (int k = 0; k < SCH; k++) {
            float dvx = DVX[k], dvy = DVY[k];
            float r2  = fmaf(dvx, dvx, fmaf(dvy, dvy, kEPS));
            float ir  = rsqrtf(r2);
            float r   = r2 * ir;
            // dz at step start (Z_steps is NOT cumulative): dz = dz0 + dv * DELTA
            float dzx = fmaf(dvx, kDELTA, dzx0);
            float dzy = fmaf(dvy, kDELTA, dzy0);
            float zdv = fmaf(dzx, dvx, dzy * dvy);
            float q2v = fmaf(dzx, dzx, dzy * dzy);          // |dz|^2 = c + x2^2
            float x2  = zdv * ir;                           // r * bshift
            float x1  = fmaf(r, kDELTA, x2);                // r * (DELTA + bshift)
            float cc  = fmaf(-x2, x2, q2v);
            // |dz + DELTA*dv|^2 = c + x1^2
            float q1v = fmaf(2.0f * kDELTA, zdv, fmaf(kDELTA * kDELTA, r2, q2v));
            // erf(x1)-erf(x2) via A&S 7.1.25 with exp fusion; ONE division for both:
            float ax1 = fabsf(x1), ax2 = fabsf(x2);
            float d1  = fmaf(kP3, ax1, 1.0f);
            float d2  = fmaf(kP3, ax2, 1.0f);
            float inv = __fdividef(1.0f, d1 * d2);
            float t1  = inv * d2;
            float t2  = inv * d1;
            float T1  = t1 * fmaf(t1, fmaf(t1, kB3, kB2), kB1);
            float T2  = t2 * fmaf(t2, fmaf(t2, kB3, kB2), kB1);
            float s1  = copysignf(1.0f, x1);
            float s2  = copysignf(1.0f, x2);
            float E1  = __expf(bb - q1v);
            float E2  = __expf(bb - q2v);
            float mid = (s1 - s2) * __expf(bb - cc);
            accs[k] = (kSQPI_2 * ir) * (mid + fmaf(s2 * T2, E2, -(s1 * T1) * E1));
        }
        // s = 0 contributes exactly 0 in the reference (time_deltas[0] == 0)
        if (s_beg == 0) accs[0] = 0.f;
        facc = (accs[0] + accs[1]) + (accs[2] + accs[3]);
    }

    double tot = block_reduce_f(facc, sred);
    if (tid == 0) {
        st_cg_f64(&g_part[blockIdx.x], tot);          // L2-direct partial
        unsigned done = atom_inc_acq_rel(&g_count);   // release: orders the store
        s_last = (done == (unsigned)(NB - 1));        // acquire: orders our reads
    }
    __syncthreads();

    if (s_last) {
        double a2 = 0.0;
        for (int b = tid; b < NB; b += TPB)
            a2 += ld_cg_f64(&g_part[b]);              // L2-direct, no stale L1
        double t2 = block_reduce_d(a2, sred);
        if (tid == 0) {
            out[0] = (float)((double)P * (double)E * (double)beta[0] - t2);
            g_count = 0;  // reset for next (graph-replayed) launch
        }
    }
}

extern "C" void kernel_launch(void* const* d_in, const int* in_sizes, int n_in,
                              void* d_out, int out_size)
{
    const float* beta = (const float*)d_in[0];
    const float* z0   = (const float*)d_in[1];
    const float* v0   = (const float*)d_in[2];
    const float* ev   = (const float*)d_in[3];
    // d_in[4] = t0, d_in[5] = tn : unused by the math
    const int*   pi   = (const int*)d_in[6];
    const int*   pj   = (const int*)d_in[7];

    const int E = in_sizes[3];
    const int P = in_sizes[6];

    const int NB_EV = ((P + TPB - 1) / TPB) * SPLIT_EV;    // 64 for P=4000
    const int NB_NE = (NPAIRS * NCH + TPB - 1) / TPB;      // 508
    const int NB    = NB_EV + NB_NE;                       // 572 (single wave)

    k_all<<<NB, TPB>>>(beta, z0, v0, ev, pi, pj, P, E, NB_EV, NB, (float*)d_out);
}

// round 17
// speedup vs baseline: 1.0114x; 1.0114x over previous
#include <cuda_runtime.h>

// Problem constants (fixed shapes for this problem instance)
#define NPTS     128                    // n_points
#define STEPS    64                     // velocity steps
#define NPAIRS   ((NPTS*(NPTS-1))/2)    // 8128 upper-tri pairs
#define NCH      16                     // s-chunks per (i,j) pair (non-event)
#define SCH      (STEPS/NCH)            // 4 steps per chunk (one float4)
#define TPB      256
#define PPB      (TPB/NCH)              // 16 pairs per non-event block
#define SPLIT_EV 4                      // step-splits per event pair-block
#define EV_STEPS (STEPS/SPLIT_EV)       // 16 steps per event block
#define EV_Q     (EV_STEPS/4)           // 4 float4 iters per event block
#define VSTRIDE  5                      // float4 stride per staged row (bank padding)

static __device__ __constant__ float kDELTA  = (float)(100.0 / 63.0);  // fp32 MAX_TIME/(STEPS-1)
static __device__ __constant__ float kINVD   = 0.63f;                  // 1/kDELTA (63/100), ~1ulp
static __device__ __constant__ float kEPS    = 1e-9f;
static __device__ __constant__ float kSQPI_2 = 0.8862269254527580f;    // sqrt(pi)/2
#define LOG2E 1.4426950408889634f
// Abramowitz & Stegun 7.1.25 erf approximation (|abs err| < 2.5e-5)
static __device__ __constant__ float kP3 = 0.47047f;
static __device__ __constant__ float kB1 = 0.3480242f;
static __device__ __constant__ float kB2 = -0.0958798f;
static __device__ __constant__ float kB3 = 0.7478556f;

// Per-block double partials + completion counter.
// g_count self-resets to 0 at end of every launch -> graph-replay deterministic.
__device__ double   g_part[1024];
__device__ unsigned g_count = 0;

typedef unsigned long long u64;

// ---- f32x2 packed helpers (sm_103a packed fp32; ptxas won't auto-fuse) ----
__device__ __forceinline__ u64 pk2(float a, float b) {
    u64 r; asm("mov.b64 %0, {%1, %2};" : "=l"(r) : "f"(a), "f"(b)); return r;
}
__device__ __forceinline__ void upk2(float& a, float& b, u64 v) {
    asm("mov.b64 {%0, %1}, %2;" : "=f"(a), "=f"(b) : "l"(v));
}
__device__ __forceinline__ u64 fma2(u64 a, u64 b, u64 c) {
    u64 d; asm("fma.rn.f32x2 %0, %1, %2, %3;" : "=l"(d) : "l"(a), "l"(b), "l"(c)); return d;
}
__device__ __forceinline__ u64 mul2(u64 a, u64 b) {
    u64 d; asm("mul.rn.f32x2 %0, %1, %2;" : "=l"(d) : "l"(a), "l"(b)); return d;
}
__device__ __forceinline__ float frcp(float x) {
    float y; asm("rcp.approx.f32 %0, %1;" : "=f"(y) : "f"(x)); return y;
}
__device__ __forceinline__ float fex2(float x) {
    float y; asm("ex2.approx.f32 %0, %1;" : "=f"(y) : "f"(x)); return y;
}

// fp32 intra-warp reduce (cheap FADD tail), double only across the 8 warps.
__device__ __forceinline__ double block_reduce_f(float v, double* shd) {
    int tid = threadIdx.x;
    #pragma unroll
    for (int off = 16; off > 0; off >>= 1)
        v += __shfl_down_sync(0xffffffffu, v, off);
    if ((tid & 31) == 0) shd[tid >> 5] = (double)v;
    __syncthreads();
    double d = 0.0;
    if (tid < 8) {
        d = shd[tid];
        #pragma unroll
        for (int off = 4; off > 0; off >>= 1)
            d += __shfl_down_sync(0xffu, d, off);
    }
    return d;  // valid on tid 0
}

__device__ __forceinline__ double block_reduce_d(double v, double* sh) {
    int tid = threadIdx.x;
    #pragma unroll
    for (int off = 16; off > 0; off >>= 1)
        v += __shfl_down_sync(0xffffffffu, v, off);
    if ((tid & 31) == 0) sh[tid >> 5] = v;
    __syncthreads();
    if (tid < 8) {
        v = sh[tid];
        #pragma unroll
        for (int off = 4; off > 0; off >>= 1)
            v += __shfl_down_sync(0xffu, v, off);
    }
    return v;  // valid on tid 0
}

// L2-direct store / load (bypass L1) + acq_rel completion counter.
__device__ __forceinline__ void st_cg_f64(double* p, double v) {
    asm volatile("st.global.cg.f64 [%0], %1;" :: "l"(p), "d"(v) : "memory");
}
__device__ __forceinline__ double ld_cg_f64(const double* p) {
    double v;
    asm volatile("ld.global.cg.f64 %0, [%1];" : "=d"(v) : "l"(p) : "memory");
    return v;
}
__device__ __forceinline__ unsigned atom_inc_acq_rel(unsigned* p) {
    unsigned d;
    asm volatile("atom.acq_rel.gpu.global.add.u32 %0, [%1], 1;"
                 : "=r"(d) : "l"(p) : "memory");
    return d;
}

// Two integral steps, packed 2-wide. Returns the two step values.
__device__ __forceinline__ float2 step_pair(
    float dvxa, float dvxb, float dvya, float dvyb,
    float dzx0, float dzy0, float bbl2e)
{
    const u64 ceps  = pk2(kEPS, kEPS);
    const u64 cdl   = pk2(kDELTA, kDELTA);
    const u64 cdl2  = pk2(kDELTA * kDELTA, kDELTA * kDELTA);
    const u64 c2dl  = pk2(2.0f * kDELTA, 2.0f * kDELTA);
    const u64 cneg1 = pk2(-1.0f, -1.0f);
    const u64 cone  = pk2(1.0f, 1.0f);
    const u64 cp3   = pk2(kP3, kP3);
    const u64 cb1   = pk2(kB1, kB1);
    const u64 cb2   = pk2(kB2, kB2);
    const u64 cb3   = pk2(kB3, kB3);
    const u64 cnl2e = pk2(-LOG2E, -LOG2E);
    const u64 cbb   = pk2(bbl2e, bbl2e);

    u64 Pdvx = pk2(dvxa, dvxb);
    u64 Pdvy = pk2(dvya, dvyb);
    u64 r2   = fma2(Pdvx, Pdvx, fma2(Pdvy, Pdvy, ceps));
    float r2a, r2b; upk2(r2a, r2b, r2);
    float ira = rsqrtf(r2a), irb = rsqrtf(r2b);
    u64 Pir  = pk2(ira, irb);
    u64 Pr   = mul2(r2, Pir);
    u64 Pdzx = fma2(Pdvx, cdl, pk2(dzx0, dzx0));
    u64 Pdzy = fma2(Pdvy, cdl, pk2(dzy0, dzy0));
    u64 Pzdv = fma2(Pdzx, Pdvx, mul2(Pdzy, Pdvy));
    u64 Pq2  = fma2(Pdzx, Pdzx, mul2(Pdzy, Pdzy));   // |dz|^2 = c + x2^2
    u64 Px2  = mul2(Pzdv, Pir);                      // r * bshift
    u64 Px1  = fma2(Pr, cdl, Px2);                   // r * (DELTA + bshift)
    u64 Pnx2 = mul2(Px2, cneg1);
    u64 Pcc  = fma2(Px2, Pnx2, Pq2);
    u64 Pq1  = fma2(Pzdv, c2dl, fma2(r2, cdl2, Pq2)); // |dz + DELTA*dv|^2
    // erf via A&S 7.1.25, shared-reciprocal trick, packed:
    u64 Pax1 = Px1 & 0x7FFFFFFF7FFFFFFFULL;
    u64 Pax2 = Px2 & 0x7FFFFFFF7FFFFFFFULL;
    u64 Pd1  = fma2(cp3, Pax1, cone);
    u64 Pd2  = fma2(cp3, Pax2, cone);
    u64 Pdd  = mul2(Pd1, Pd2);
    float dda, ddb; upk2(dda, ddb, Pdd);
    u64 Pinv = pk2(frcp(dda), frcp(ddb));
    u64 Pt1  = mul2(Pinv, Pd2);
    u64 Pt2  = mul2(Pinv, Pd1);
    u64 PT1  = mul2(Pt1, fma2(Pt1, fma2(Pt1, cb3, cb2), cb1));
    u64 PT2  = mul2(Pt2, fma2(Pt2, fma2(Pt2, cb3, cb2), cb1));
    // exp args in log2 domain (log2e folded into packed constants):
    u64 Pe1 = fma2(Pq1, cnl2e, cbb);
    u64 Pe2 = fma2(Pq2, cnl2e, cbb);
    u64 Pec = fma2(Pcc, cnl2e, cbb);
    float e1a, e1b, e2a, e2b, eca, ecb;
    upk2(e1a, e1b, Pe1); upk2(e2a, e2b, Pe2); upk2(eca, ecb, Pec);
    float E1a = fex2(e1a), E1b = fex2(e1b);
    float E2a = fex2(e2a), E2b = fex2(e2b);
    float Ema = fex2(eca), Emb = fex2(ecb);
    float x1a, x1b, x2a, x2b, T1a, T1b, T2a, T2b;
    upk2(x1a, x1b, Px1); upk2(x2a, x2b, Px2);
    upk2(T1a, T1b, PT1); upk2(T2a, T2b, PT2);

    float2 outv;
    {
        float s1 = copysignf(1.0f, x1a), s2 = copysignf(1.0f, x2a);
        float mid = (s1 - s2) * Ema;
        outv.x = (kSQPI_2 * ira) * (mid + fmaf(s2 * T2a, E2a, -(s1 * T1a) * E1a));
    }
    {
        float s1 = copysignf(1.0f, x1b), s2 = copysignf(1.0f, x2b);
        float mid = (s1 - s2) * Emb;
        outv.y = (kSQPI_2 * irb) * (mid + fmaf(s2 * T2b, E2b, -(s1 * T1b) * E1b));
    }
    return outv;
}

__global__ void __launch_bounds__(TPB)
k_all(const float* __restrict__ beta,
      const float* __restrict__ z0,
      const float* __restrict__ v0,
      const float* __restrict__ ev,
      const int*   __restrict__ pi,
      const int*   __restrict__ pj,
      int P, int E, int NB_EV, int NB,
      float* __restrict__ out)
{
    // All shared declared at kernel scope.
    __shared__ double sred[8];
    __shared__ bool   s_last;
    // Event branch: staged v0 quarter-slice. Comp-major + stride-5 padding.
    __shared__ __align__(16) float4 sV[2 * NPTS * VSTRIDE];   // 20 KB
    __shared__ __align__(16) float  sZ[2 * NPTS];             // 1 KB
    __shared__ __align__(16) float  sS1[STEPS];
    __shared__ __align__(16) float  sS2[STEPS];
    // Non-event branch:
    __shared__ int   sIo[PPB], sJo[PPB];
    __shared__ float sDZX[PPB], sDZY[PPB];

    const int tid = threadIdx.x;
    float facc = 0.f;     // per-thread fp32 partial

    if ((int)blockIdx.x < NB_EV) {
        // ---------------- event (pair) term ----------------
        const int pb      = blockIdx.x >> 2;          // /SPLIT_EV
        const int quarter = blockIdx.x & (SPLIT_EV-1);
        const int lo      = quarter * EV_STEPS;       // step range [lo, lo+16)
        const int q_beg   = quarter * EV_Q;           // float4 col range in v0 rows

        if (tid < EV_STEPS) { sS1[lo + tid] = 0.f; sS2[lo + tid] = 0.f; }

        // Stage this quarter's v0 slice + z0 into shared (coalesced, one-time).
        {
            const float4* g = (const float4*)v0;       // row stride = 16 float4
            const int point = tid & (NPTS - 1);
            const int comp  = tid >> 7;
            const int grow  = 2 * point + comp;
            const int srow  = comp * NPTS + point;
            #pragma unroll
            for (int k = 0; k < EV_Q; k++)
                sV[srow * VSTRIDE + k] = g[grow * 16 + q_beg + k];
            if (tid < (2 * NPTS) / 4)
                ((float4*)sZ)[tid] = ((const float4*)z0)[tid];
        }
        __syncthreads();

        // Histogram of event times restricted to this block's step range.
        {
            const float4* ev4 = (const float4*)ev;
            const int nq = E >> 2;
            #pragma unroll
            for (int q = tid; q < nq; q += TPB) {
                float4 t4 = ev4[q];
                #pragma unroll
                for (int u = 0; u < 4; u++) {
                    float t  = (u == 0) ? t4.x : (u == 1) ? t4.y : (u == 2) ? t4.z : t4.w;
                    float tv = t * kINVD;          // ~1ulp vs ref's fp32 divide
                    float f  = floorf(tv);
                    int   s  = (int)f;
                    s = max(0, min(STEPS - 1, s));
                    if (s >= lo && s < lo + EV_STEPS) {
                        float a = (s == 0 ? 0.0f : kDELTA) + (tv - f);  // td[s] + frac
                        atomicAdd(&sS1[s], a);
                        atomicAdd(&sS2[s], a * a);
                    }
                }
            }
        }
        __syncthreads();

        const int p = pb * TPB + tid;
        if (p < P) {
            const int i = pi[p], j = pj[p];
            const float dzx = sZ[2*i]   - sZ[2*j];
            const float dzy = sZ[2*i+1] - sZ[2*j+1];
            const float4* S1 = (const float4*)sS1;
            const float4* S2 = (const float4*)sS2;
            float a0 = 0.f, a1 = 0.f, a2 = 0.f, a3 = 0.f;
            #pragma unroll
            for (int k = 0; k < EV_Q; k++) {
                float4 ax = sV[i * VSTRIDE + k];                 // x row, point i
                float4 ay = sV[(NPTS + i) * VSTRIDE + k];        // y row, point i
                float4 bx = sV[j * VSTRIDE + k];
                float4 by = sV[(NPTS + j) * VSTRIDE + k];
                float4 h1 = S1[q_beg + k], h2 = S2[q_beg + k];
                float dvx, dvy, B, C;
                dvx = ax.x - bx.x; dvy = ay.x - by.x;
                B = fmaf(dzx, dvx, dzy * dvy); C = fmaf(dvx, dvx, dvy * dvy);
                a0 += fmaf(2.0f * h1.x, B, h2.x * C);
                dvx = ax.y - bx.y; dvy = ay.y - by.y;
                B = fmaf(dzx, dvx, dzy * dvy); C = fmaf(dvx, dvx, dvy * dvy);
                a1 += fmaf(2.0f * h1.y, B, h2.y * C);
                dvx = ax.z - bx.z; dvy = ay.z - by.z;
                B = fmaf(dzx, dvx, dzy * dvy); C = fmaf(dvx, dvx, dvy * dvy);
                a2 += fmaf(2.0f * h1.z, B, h2.z * C);
                dvx = ax.w - bx.w; dvy = ay.w - by.w;
                B = fmaf(dzx, dvx, dzy * dvy); C = fmaf(dvx, dvx, dvy * dvy);
                a3 += fmaf(2.0f * h1.w, B, h2.w * C);
            }
            facc = (a0 + a1) + (a2 + a3);
            if (quarter == 0)   // E * |dz0|^2 term counted exactly once per pair
                facc += (float)E * fmaf(dzx, dzx, dzy * dzy);
        }
    } else {
        // ---------------- non-event (integral) term ----------------
        // Each block covers PPB=16 consecutive dense-tri pairs x NCH=16 chunks.
        const int base_p = (blockIdx.x - NB_EV) * PPB;

        if (tid < PPB) {
            const int p = base_p + tid;
            // Decode dense upper-tri index -> (i, j), i < j, N = 128.
            int i = (int)((255.0f - sqrtf(65025.0f - 8.0f * (float)p)) * 0.5f);
            i = max(0, min(126, i));
            int off = (i * (255 - i)) >> 1;
            if (off > p)                   { i--; off = (i * (255 - i)) >> 1; }
            else if (off + (127 - i) <= p) { off += 127 - i; i++; }
            const int j = i + 1 + (p - off);
            sIo[tid]  = 2 * i * STEPS;
            sJo[tid]  = 2 * j * STEPS;
            sDZX[tid] = z0[2*i]   - z0[2*j];
            sDZY[tid] = z0[2*i+1] - z0[2*j+1];
        }
        __syncthreads();

        const int pp    = tid >> 4;          // pair slot 0..15
        const int chunk = tid & (NCH - 1);   // 0..15
        const int io = sIo[pp], jo = sJo[pp];
        const float dzx0 = sDZX[pp], dzy0 = sDZY[pp];
        const float bbl2e = beta[0] * LOG2E;
        const int s_beg  = chunk * SCH;      // multiple of 4 -> 16B aligned
        const float4 vx_i = *(const float4*)(v0 + io + s_beg);
        const float4 vy_i = *(const float4*)(v0 + io + STEPS + s_beg);
        const float4 vx_j = *(const float4*)(v0 + jo + s_beg);
        const float4 vy_j = *(const float4*)(v0 + jo + STEPS + s_beg);

        // Packed 2-wide: steps {0,1} and {2,3}.
        float2 v01 = step_pair(vx_i.x - vx_j.x, vx_i.y - vx_j.y,
                               vy_i.x - vy_j.x, vy_i.y - vy_j.y,
                               dzx0, dzy0, bbl2e);
        float2 v23 = step_pair(vx_i.z - vx_j.z, vx_i.w - vx_j.w,
                               vy_i.z - vy_j.z, vy_i.w - vy_j.w,
                               dzx0, dzy0, bbl2e);
        // s = 0 contributes exactly 0 in the reference (time_deltas[0] == 0)
        if (s_beg == 0) v01.x = 0.f;
        facc = (v01.x + v01.y) + (v23.x + v23.y);
    }

    double tot = block_reduce_f(facc, sred);
    if (tid == 0) {
        st_cg_f64(&g_part[blockIdx.x], tot);          // L2-direct partial
        unsigned done = atom_inc_acq_rel(&g_count);   // release: orders the store
        s_last = (done == (unsigned)(NB - 1));        // acquire: orders our reads
    }
    __syncthreads();

    if (s_last) {
        double a2 = 0.0;
        for (int b = tid; b < NB; b += TPB)
            a2 += ld_cg_f64(&g_part[b]);              // L2-direct, no stale L1
        double t2 = block_reduce_d(a2, sred);
        if (tid == 0) {
            out[0] = (float)((double)P * (double)E * (double)beta[0] - t2);
            g_count = 0;  // reset for next (graph-replayed) launch
        }
    }
}

extern "C" void kernel_launch(void* const* d_in, const int* in_sizes, int n_in,
                              void* d_out, int out_size)
{
    const float* beta = (const float*)d_in[0];
    const float* z0   = (const float*)d_in[1];
    const float* v0   = (const float*)d_in[2];
    const float* ev   = (const float*)d_in[3];
    // d_in[4] = t0, d_in[5] = tn : unused by the math
    const int*   pi   = (const int*)d_in[6];
    const int*   pj   = (const int*)d_in[7];

    const int E = in_sizes[3];
    const int P = in_sizes[6];

    const int NB_EV = ((P + TPB - 1) / TPB) * SPLIT_EV;    // 64 for P=4000
    const int NB_NE = (NPAIRS * NCH + TPB - 1) / TPB;      // 508
    const int NB    = NB_EV + NB_NE;                       // 572 (single wave)

    k_all<<<NB, TPB>>>(beta, z0, v0, ev, pi, pj, P, E, NB_EV, NB, (float*)d_out);
}